// round 12
// baseline (speedup 1.0000x reference)
#include <cuda_runtime.h>
#include <cuda_fp16.h>
#include <cuda_bf16.h>
#include <cstdint>

#define N_NODES  100000
#define N_EDGES  1600000
#define D_H      128
#define N_GRAPHS 128

#define SCAN_BLK 1024
#define NBLK     ((N_NODES + SCAN_BLK - 1) / SCAN_BLK)   // 98

#define TILE_M   128
#define N_TILES  ((N_NODES + TILE_M - 1) / TILE_M)       // 782

#define LDAH     136   // padded row stride in halves (272B) for smem A/B tiles
#define LDD      130   // padded row stride in floats for smem D (EVEN -> float2 aligned)

// ---------------- device scratch (zero-initialized at module load) ----------------
// INVARIANT: every kernel_launch call leaves g_deg, g_pooled, g_blk_pack zeroed
// (done in k_final).
__device__ int    g_deg[N_NODES];
__device__ float  g_dinv[N_NODES];
__device__ int    g_rowstart[N_NODES + 1];
__device__ int    g_cursor[N_NODES];
__device__ int    g_col[N_EDGES];
__device__ unsigned long long g_blk_pack[NBLK];     // lookback: (state<<32)|value, 1=agg 2=prefix
__device__ __half g_xh[(size_t)N_NODES * D_H];      // xs = dinv * x, fp16
__device__ __half g_wt[D_H * D_H];                  // W^T row-major: g_wt[n*128+k] = W[k][n]
__device__ float  g_pooled[N_GRAPHS * D_H];
__device__ int    g_bound[N_GRAPHS + 1];            // graph start offsets (batch sorted)

// ---------------- helpers ----------------
__device__ __forceinline__ uint32_t smem_u32(const void* p) {
    uint32_t a;
    asm("{ .reg .u64 t; cvta.to.shared.u64 t, %1; cvt.u32.u64 %0, t; }" : "=r"(a) : "l"(p));
    return a;
}
__device__ __forceinline__ float4 ldh4(const __half* p) {
    uint2 u = *reinterpret_cast<const uint2*>(p);
    __half2 a = *reinterpret_cast<__half2*>(&u.x);
    __half2 b = *reinterpret_cast<__half2*>(&u.y);
    float2 fa = __half22float2(a), fb = __half22float2(b);
    return make_float4(fa.x, fa.y, fb.x, fb.y);
}

// ---------------- fused preprocessing: deg atomics + graph bounds + W prep ----------------
__global__ void k_pre(const int* __restrict__ ei, const int* __restrict__ batch,
                      const float* __restrict__ W) {
    int i = blockIdx.x * blockDim.x + threadIdx.x;
    if (i < N_EDGES) atomicAdd(&g_deg[ei[N_EDGES + i]], 1);
    if (i < N_NODES) {
        int b0 = batch[i];
        int b1 = (i + 1 < N_NODES) ? batch[i + 1] : N_GRAPHS;
        if (i == 0)
            for (int g = 0; g <= b0; g++) g_bound[g] = 0;
        for (int g = b0 + 1; g <= b1; g++) g_bound[g] = i + 1;
    }
    if (i < D_H * D_H) {
        int k = i >> 7, n = i & 127;                   // coalesced read of W[k][n]
        g_wt[n * D_H + k] = __float2half_rn(W[i]);
    }
}

// ---------------- fused: decoupled-lookback scan + dinv + xs = dinv*x -> fp16 ----------------
__global__ __launch_bounds__(SCAN_BLK) void k_scanx(const float* __restrict__ x) {
    __shared__ int   ws[32];
    __shared__ float sdinv[SCAN_BLK];
    __shared__ int   s_excl;

    int t = threadIdx.x, b = blockIdx.x;
    int base = b * SCAN_BLK;
    int i = base + t;

    int d = (i < N_NODES) ? g_deg[i] : 0;
    float dv = rsqrtf((float)(d + 1));
    sdinv[t] = dv;
    if (i < N_NODES) g_dinv[i] = dv;

    // block-wide inclusive scan of d
    int v = d;
    #pragma unroll
    for (int o = 1; o < 32; o <<= 1) { int n = __shfl_up_sync(0xffffffffu, v, o); if ((t & 31) >= o) v += n; }
    if ((t & 31) == 31) ws[t >> 5] = v;
    __syncthreads();
    if (t < 32) {
        int s = ws[t];
        #pragma unroll
        for (int o = 1; o < 32; o <<= 1) { int n = __shfl_up_sync(0xffffffffu, s, o); if (t >= o) s += n; }
        ws[t] = s;
    }
    __syncthreads();
    int warpoff = (t >= 32) ? ws[(t >> 5) - 1] : 0;
    int lexcl = v - d + warpoff;          // exclusive within block
    int total = ws[31];                   // block aggregate

    // decoupled lookback (thread 0); packed 64-bit state+value
    if (t == 0) {
        volatile unsigned long long* pk = (volatile unsigned long long*)g_blk_pack;
        if (b == 0) {
            pk[0] = (2ULL << 32) | (unsigned)total;
            s_excl = 0;
        } else {
            pk[b] = (1ULL << 32) | (unsigned)total;
            int excl = 0;
            for (int j = b - 1; j >= 0; ) {
                unsigned long long p;
                do { p = pk[j]; } while ((p >> 32) == 0);
                excl += (int)(unsigned)p;
                if ((p >> 32) == 2) break;
                j--;
            }
            pk[b] = (2ULL << 32) | (unsigned)(excl + total);
            s_excl = excl;
        }
    }
    __syncthreads();
    int bexcl = s_excl;

    if (i < N_NODES) {
        int rs = bexcl + lexcl;
        g_rowstart[i] = rs;
        g_cursor[i] = rs;
    }
    if (b == NBLK - 1 && t == 0) g_rowstart[N_NODES] = N_EDGES;

    // xs phase: scale this block's x rows by dinv, convert to fp16
    int nvalid = N_NODES - base; if (nvalid > SCAN_BLK) nvalid = SCAN_BLK;
    if (nvalid <= 0) return;
    const float4* xp = reinterpret_cast<const float4*>(x) + (size_t)base * 32;
    uint2* op = reinterpret_cast<uint2*>(g_xh) + (size_t)base * 32;
    int nf4 = nvalid * 32;
    for (int idx = t; idx < nf4; idx += SCAN_BLK) {
        float s = sdinv[idx >> 5];
        float4 f = xp[idx];
        __half2 h0 = __floats2half2_rn(f.x * s, f.y * s);
        __half2 h1 = __floats2half2_rn(f.z * s, f.w * s);
        uint2 u;
        u.x = *reinterpret_cast<unsigned*>(&h0);
        u.y = *reinterpret_cast<unsigned*>(&h1);
        op[idx] = u;
    }
}

__global__ void k_fill(const int* __restrict__ ei) {
    int e = blockIdx.x * blockDim.x + threadIdx.x;
    if (e >= N_EDGES) return;
    int s = ei[e], d = ei[N_EDGES + e];
    int p = atomicAdd(&g_cursor[d], 1);
    g_col[p] = s;
}

// ---------------- fused: pull-gather aggregation + mma.sync GEMM + epilogue ----------------
// smem layout (bytes from dynamic base):
#define SM_BIAS   0                       // 128 f32
#define SM_PRELU  512                     // 128 f32
#define SM_BATCH  1024                    // 128 int
#define SM_A      2048                    // 128 x LDAH halves = 34816B (padded)
#define SM_B      (SM_A + 128 * LDAH * 2) // 34816B
#define SM_D      SM_A                    // reuse: 128 x LDD f32 = 66560B
#define SM_TOTAL  (SM_B + 128 * LDAH * 2) // 71680

#define LDSM_X4(r0, r1, r2, r3, addr) \
    asm volatile("ldmatrix.sync.aligned.m8n8.x4.shared.b16 {%0,%1,%2,%3}, [%4];" \
                 : "=r"(r0), "=r"(r1), "=r"(r2), "=r"(r3) : "r"(addr))

#define MMA16816(c, a0, a1, a2, a3, b0, b1) \
    asm volatile("mma.sync.aligned.m16n8k16.row.col.f32.f16.f16.f32 " \
                 "{%0,%1,%2,%3}, {%4,%5,%6,%7}, {%8,%9}, {%0,%1,%2,%3};" \
                 : "+f"((c)[0]), "+f"((c)[1]), "+f"((c)[2]), "+f"((c)[3]) \
                 : "r"(a0), "r"(a1), "r"(a2), "r"(a3), "r"(b0), "r"(b1))

__global__ __launch_bounds__(256) void k_aggmma(const float* __restrict__ bias,
                                                const float* __restrict__ pa,
                                                const int* __restrict__ batch) {
    extern __shared__ __align__(1024) char sm[];
    int t = threadIdx.x;
    int w = t >> 5, l = t & 31;
    int row0 = blockIdx.x * TILE_M;

    // stage B = W^T + params while gather warms up
    for (int i = t; i < 2048; i += 256) {
        int r = i >> 4, c8 = i & 15;
        uint4 vb = reinterpret_cast<const uint4*>(g_wt)[i];
        *reinterpret_cast<uint4*>(sm + SM_B + (r * LDAH + c8 * 8) * 2) = vb;
    }
    for (int i = t; i < D_H; i += 256) {
        reinterpret_cast<float*>(sm + SM_BIAS)[i] = bias[i];
        reinterpret_cast<float*>(sm + SM_PRELU)[i] = pa[i];
        int rg = row0 + i;
        reinterpret_cast<int*>(sm + SM_BATCH)[i] = batch[rg < N_NODES ? rg : N_NODES - 1];
    }

    // gather-aggregate this CTA's 128 rows straight into the smem A tile:
    // warp w handles tile rows w*16 .. w*16+15; lane l covers features 4l..4l+3
    {
        const __half* xp = g_xh;
        #pragma unroll 1
        for (int rl = 0; rl < 16; rl++) {
            int r = w * 16 + rl;
            int node = row0 + r;
            float4 acc = make_float4(0.f, 0.f, 0.f, 0.f);
            if (node < N_NODES) {
                acc = ldh4(xp + (size_t)node * D_H + l * 4);   // self term (dinv-scaled)
                float wd = g_dinv[node];
                int e = g_rowstart[node], r1 = g_rowstart[node + 1];
                for (; e + 4 <= r1; e += 4) {
                    int s0 = g_col[e], s1 = g_col[e + 1], s2 = g_col[e + 2], s3 = g_col[e + 3];
                    float4 f0 = ldh4(xp + (size_t)s0 * D_H + l * 4);
                    float4 f1 = ldh4(xp + (size_t)s1 * D_H + l * 4);
                    float4 f2 = ldh4(xp + (size_t)s2 * D_H + l * 4);
                    float4 f3 = ldh4(xp + (size_t)s3 * D_H + l * 4);
                    acc.x += (f0.x + f1.x) + (f2.x + f3.x);
                    acc.y += (f0.y + f1.y) + (f2.y + f3.y);
                    acc.z += (f0.z + f1.z) + (f2.z + f3.z);
                    acc.w += (f0.w + f1.w) + (f2.w + f3.w);
                }
                for (; e < r1; e++) {
                    int s0 = g_col[e];
                    float4 f0 = ldh4(xp + (size_t)s0 * D_H + l * 4);
                    acc.x += f0.x; acc.y += f0.y; acc.z += f0.z; acc.w += f0.w;
                }
                acc.x *= wd; acc.y *= wd; acc.z *= wd; acc.w *= wd;
            }
            __half2 h0 = __floats2half2_rn(acc.x, acc.y);
            __half2 h1 = __floats2half2_rn(acc.z, acc.w);
            uint2 u;
            u.x = *reinterpret_cast<unsigned*>(&h0);
            u.y = *reinterpret_cast<unsigned*>(&h1);
            *reinterpret_cast<uint2*>(sm + SM_A + (r * LDAH + l * 4) * 2) = u;
        }
    }
    __syncthreads();

    uint32_t sA = smem_u32(sm + SM_A);
    uint32_t sB = smem_u32(sm + SM_B);

    // preload all 8 A k-chunk fragments for this warp's 16-row band
    uint32_t a[8][4];
    {
        uint32_t base = sA + ((w * 16 + (l & 15)) * LDAH + (l >> 4) * 8) * 2;
        #pragma unroll
        for (int k = 0; k < 8; k++)
            LDSM_X4(a[k][0], a[k][1], a[k][2], a[k][3], base + k * 32);
    }

    float acc[16][4];
    #pragma unroll
    for (int nb = 0; nb < 16; nb++)
        #pragma unroll
        for (int j = 0; j < 4; j++) acc[nb][j] = 0.f;

    uint32_t bbase = sB + ((((l >> 4) * 8) + (l & 7)) * LDAH + ((l >> 3) & 1) * 8) * 2;
    #pragma unroll
    for (int k = 0; k < 8; k++) {
        #pragma unroll
        for (int nbp = 0; nbp < 8; nbp++) {
            uint32_t b0, b1, b2, b3;
            LDSM_X4(b0, b1, b2, b3, bbase + (nbp * 16 * LDAH) * 2 + k * 32);
            MMA16816(acc[2 * nbp], a[k][0], a[k][1], a[k][2], a[k][3], b0, b1);
            MMA16816(acc[2 * nbp + 1], a[k][0], a[k][1], a[k][2], a[k][3], b2, b3);
        }
    }

    __syncthreads();   // done reading A/B; D region reuses A/B smem

    // epilogue: +bias, PReLU, row sumsq (quad shfl), normalize, stage to smem D
    {
        const float* sBias = reinterpret_cast<const float*>(sm + SM_BIAS);
        const float* sPrelu = reinterpret_cast<const float*>(sm + SM_PRELU);
        float* sD = reinterpret_cast<float*>(sm + SM_D);
        int quad = l >> 2, qlane = l & 3;
        int r_lo = w * 16 + quad, r_hi = r_lo + 8;

        float ss_lo = 0.f, ss_hi = 0.f;
        #pragma unroll
        for (int nb = 0; nb < 16; nb++) {
            int c0 = nb * 8 + qlane * 2;
            float b0 = sBias[c0], b1 = sBias[c0 + 1];
            float p0 = sPrelu[c0], p1 = sPrelu[c0 + 1];
            float v0 = acc[nb][0] + b0; v0 = v0 > 0.f ? v0 : v0 * p0;
            float v1 = acc[nb][1] + b1; v1 = v1 > 0.f ? v1 : v1 * p1;
            float v2 = acc[nb][2] + b0; v2 = v2 > 0.f ? v2 : v2 * p0;
            float v3 = acc[nb][3] + b1; v3 = v3 > 0.f ? v3 : v3 * p1;
            acc[nb][0] = v0; acc[nb][1] = v1; acc[nb][2] = v2; acc[nb][3] = v3;
            ss_lo += v0 * v0 + v1 * v1;
            ss_hi += v2 * v2 + v3 * v3;
        }
        ss_lo += __shfl_xor_sync(0xffffffffu, ss_lo, 1);
        ss_lo += __shfl_xor_sync(0xffffffffu, ss_lo, 2);
        ss_hi += __shfl_xor_sync(0xffffffffu, ss_hi, 1);
        ss_hi += __shfl_xor_sync(0xffffffffu, ss_hi, 2);
        float inv_lo = rsqrtf(fmaxf(ss_lo, 1e-24f));
        float inv_hi = rsqrtf(fmaxf(ss_hi, 1e-24f));

        #pragma unroll
        for (int nb = 0; nb < 16; nb++) {
            int c0 = nb * 8 + qlane * 2;
            *reinterpret_cast<float2*>(sD + r_lo * LDD + c0) =
                make_float2(acc[nb][0] * inv_lo, acc[nb][1] * inv_lo);
            *reinterpret_cast<float2*>(sD + r_hi * LDD + c0) =
                make_float2(acc[nb][2] * inv_hi, acc[nb][3] * inv_hi);
        }
    }
    __syncthreads();

    // pooling: 2 threads per column (rows 0-63 / 64-127), run-based flush to global
    {
        int c = t & 127;
        int r0 = (t >> 7) * 64;
        int nvalid = N_NODES - row0; if (nvalid > TILE_M) nvalid = TILE_M;
        int rend = r0 + 64; if (rend > nvalid) rend = nvalid;
        const float* sD = reinterpret_cast<const float*>(sm + SM_D);
        const int* sBatch = reinterpret_cast<const int*>(sm + SM_BATCH);
        int cur = -1;
        float acc2 = 0.f;
        for (int r = r0; r < rend; r++) {
            int g = sBatch[r];
            if (g != cur) {
                if (cur >= 0) atomicAdd(&g_pooled[cur * D_H + c], acc2);
                cur = g; acc2 = 0.f;
            }
            acc2 += sD[r * LDD + c];
        }
        if (cur >= 0) atomicAdd(&g_pooled[cur * D_H + c], acc2);
    }
}

// final output + reset state (deg, pooled, lookback) for the next call
__global__ void k_final(float* __restrict__ out) {
    int i = blockIdx.x * blockDim.x + threadIdx.x;
    if (i < N_GRAPHS * D_H) {
        int g = i >> 7;
        float c = (float)(g_bound[g + 1] - g_bound[g]);
        out[i] = g_pooled[i] / fmaxf(c, 1.f);
        g_pooled[i] = 0.f;
    }
    if (i < N_NODES) g_deg[i] = 0;
    if (i < NBLK) g_blk_pack[i] = 0ULL;
}

// ---------------- launcher ----------------
extern "C" void kernel_launch(void* const* d_in, const int* in_sizes, int n_in,
                              void* d_out, int out_size) {
    const float* x     = (const float*)d_in[0];
    const int*   ei    = (const int*)d_in[1];
    const int*   batch = (const int*)d_in[2];
    const float* W     = (const float*)d_in[3];
    const float* b     = (const float*)d_in[4];
    const float* pa    = (const float*)d_in[5];
    float* out = (float*)d_out;

    cudaFuncSetAttribute(k_aggmma, cudaFuncAttributeMaxDynamicSharedMemorySize, SM_TOTAL);

    k_pre<<<(N_EDGES + 255) / 256, 256>>>(ei, batch, W);
    k_scanx<<<NBLK, SCAN_BLK>>>(x);
    k_fill<<<(N_EDGES + 255) / 256, 256>>>(ei);
    k_aggmma<<<N_TILES, 256, SM_TOTAL>>>(b, pa, batch);
    k_final<<<(N_NODES + 255) / 256, 256>>>(out);
}

// round 13
// speedup vs baseline: 1.2140x; 1.2140x over previous
#include <cuda_runtime.h>
#include <cuda_fp16.h>
#include <cuda_bf16.h>
#include <cstdint>

#define N_NODES  100000
#define N_EDGES  1600000
#define D_H      128
#define N_GRAPHS 128

#define SCAN_BLK 1024
#define NBLK     ((N_NODES + SCAN_BLK - 1) / SCAN_BLK)   // 98

#define TILE_M   128
#define N_TILES  ((N_NODES + TILE_M - 1) / TILE_M)       // 782
#define N_PAD    (N_TILES * TILE_M)                       // 100096

#define LDAH     136   // padded row stride in halves (272B) for smem A/B tiles
#define LDD      130   // padded row stride in floats for smem D (EVEN -> float2 aligned)

// ---------------- device scratch (zero-initialized at module load) ----------------
// INVARIANT: every kernel_launch call leaves g_deg, g_pooled, g_blk_pack zeroed
// (done in k_final); pad rows of g_aggh are never written -> stay zero.
__device__ int    g_deg[N_NODES];
__device__ float  g_dinv[N_NODES];
__device__ int    g_rowstart[N_NODES + 1];
__device__ int    g_cursor[N_NODES];
__device__ int    g_col[N_EDGES];
__device__ unsigned long long g_blk_pack[NBLK];     // lookback: (state<<32)|value, 1=agg 2=prefix
__device__ __half g_xh[(size_t)N_NODES * D_H];      // xs = dinv * x, fp16
__device__ __half g_aggh[(size_t)N_PAD * D_H];      // fp16 aggregated features (padded)
__device__ __half g_wt[D_H * D_H];                  // W^T row-major: g_wt[n*128+k] = W[k][n]
__device__ float  g_pooled[N_GRAPHS * D_H];
__device__ int    g_bound[N_GRAPHS + 1];            // graph start offsets (batch sorted)

// ---------------- helpers ----------------
__device__ __forceinline__ uint32_t smem_u32(const void* p) {
    uint32_t a;
    asm("{ .reg .u64 t; cvta.to.shared.u64 t, %1; cvt.u32.u64 %0, t; }" : "=r"(a) : "l"(p));
    return a;
}
__device__ __forceinline__ float4 cvt4(uint2 u) {
    __half2 a = *reinterpret_cast<__half2*>(&u.x);
    __half2 b = *reinterpret_cast<__half2*>(&u.y);
    float2 fa = __half22float2(a), fb = __half22float2(b);
    return make_float4(fa.x, fa.y, fb.x, fb.y);
}

// ---------------- fused preprocessing: deg atomics + graph bounds + W prep ----------------
__global__ void k_pre(const int* __restrict__ ei, const int* __restrict__ batch,
                      const float* __restrict__ W) {
    int i = blockIdx.x * blockDim.x + threadIdx.x;
    if (i < N_EDGES) atomicAdd(&g_deg[ei[N_EDGES + i]], 1);
    if (i < N_NODES) {
        int b0 = batch[i];
        int b1 = (i + 1 < N_NODES) ? batch[i + 1] : N_GRAPHS;
        if (i == 0)
            for (int g = 0; g <= b0; g++) g_bound[g] = 0;
        for (int g = b0 + 1; g <= b1; g++) g_bound[g] = i + 1;
    }
    if (i < D_H * D_H) {
        int k = i >> 7, n = i & 127;                   // coalesced read of W[k][n]
        g_wt[n * D_H + k] = __float2half_rn(W[i]);
    }
}

// ---------------- fused: decoupled-lookback scan + dinv + xs = dinv*x -> fp16 ----------------
__global__ __launch_bounds__(SCAN_BLK) void k_scanx(const float* __restrict__ x) {
    __shared__ int   ws[32];
    __shared__ float sdinv[SCAN_BLK];
    __shared__ int   s_excl;

    int t = threadIdx.x, b = blockIdx.x;
    int base = b * SCAN_BLK;
    int i = base + t;

    int d = (i < N_NODES) ? g_deg[i] : 0;
    float dv = rsqrtf((float)(d + 1));
    sdinv[t] = dv;
    if (i < N_NODES) g_dinv[i] = dv;

    // block-wide inclusive scan of d
    int v = d;
    #pragma unroll
    for (int o = 1; o < 32; o <<= 1) { int n = __shfl_up_sync(0xffffffffu, v, o); if ((t & 31) >= o) v += n; }
    if ((t & 31) == 31) ws[t >> 5] = v;
    __syncthreads();
    if (t < 32) {
        int s = ws[t];
        #pragma unroll
        for (int o = 1; o < 32; o <<= 1) { int n = __shfl_up_sync(0xffffffffu, s, o); if (t >= o) s += n; }
        ws[t] = s;
    }
    __syncthreads();
    int warpoff = (t >= 32) ? ws[(t >> 5) - 1] : 0;
    int lexcl = v - d + warpoff;          // exclusive within block
    int total = ws[31];                   // block aggregate

    // decoupled lookback (thread 0); packed 64-bit state+value
    if (t == 0) {
        volatile unsigned long long* pk = (volatile unsigned long long*)g_blk_pack;
        if (b == 0) {
            pk[0] = (2ULL << 32) | (unsigned)total;
            s_excl = 0;
        } else {
            pk[b] = (1ULL << 32) | (unsigned)total;
            int excl = 0;
            for (int j = b - 1; j >= 0; ) {
                unsigned long long p;
                do { p = pk[j]; } while ((p >> 32) == 0);
                excl += (int)(unsigned)p;
                if ((p >> 32) == 2) break;
                j--;
            }
            pk[b] = (2ULL << 32) | (unsigned)(excl + total);
            s_excl = excl;
        }
    }
    __syncthreads();
    int bexcl = s_excl;

    if (i < N_NODES) {
        int rs = bexcl + lexcl;
        g_rowstart[i] = rs;
        g_cursor[i] = rs;
    }
    if (b == NBLK - 1 && t == 0) g_rowstart[N_NODES] = N_EDGES;

    // xs phase: scale this block's x rows by dinv, convert to fp16
    int nvalid = N_NODES - base; if (nvalid > SCAN_BLK) nvalid = SCAN_BLK;
    if (nvalid <= 0) return;
    const float4* xp = reinterpret_cast<const float4*>(x) + (size_t)base * 32;
    uint2* op = reinterpret_cast<uint2*>(g_xh) + (size_t)base * 32;
    int nf4 = nvalid * 32;
    for (int idx = t; idx < nf4; idx += SCAN_BLK) {
        float s = sdinv[idx >> 5];
        float4 f = xp[idx];
        __half2 h0 = __floats2half2_rn(f.x * s, f.y * s);
        __half2 h1 = __floats2half2_rn(f.z * s, f.w * s);
        uint2 u;
        u.x = *reinterpret_cast<unsigned*>(&h0);
        u.y = *reinterpret_cast<unsigned*>(&h1);
        op[idx] = u;
    }
}

__global__ void k_fill(const int* __restrict__ ei) {
    int e = blockIdx.x * blockDim.x + threadIdx.x;
    if (e >= N_EDGES) return;
    int s = ei[e], d = ei[N_EDGES + e];
    int p = atomicAdd(&g_cursor[d], 1);
    g_col[p] = s;
}

// pull-mode aggregation: agg[d] = dinv[d] * ( xs[d] + sum_{s->d} xs[s] )  -> fp16
// 32-bit index math only (uint2 granularity: node*32 + lane).
__global__ void k_agg() {
    int warp = (blockIdx.x * blockDim.x + threadIdx.x) >> 5;
    int l = threadIdx.x & 31;
    if (warp >= N_NODES) return;
    uint32_t d = (uint32_t)warp;
    const uint2* __restrict__ xp = reinterpret_cast<const uint2*>(g_xh);
    float wd = g_dinv[d];
    float4 acc = cvt4(xp[d * 32u + l]);   // self term (already dinv-scaled)
    int r0 = g_rowstart[d], r1 = g_rowstart[d + 1];
    int e = r0;
    for (; e + 4 <= r1; e += 4) {
        uint32_t s0 = (uint32_t)g_col[e]     * 32u + l;
        uint32_t s1 = (uint32_t)g_col[e + 1] * 32u + l;
        uint32_t s2 = (uint32_t)g_col[e + 2] * 32u + l;
        uint32_t s3 = (uint32_t)g_col[e + 3] * 32u + l;
        float4 f0 = cvt4(xp[s0]);
        float4 f1 = cvt4(xp[s1]);
        float4 f2 = cvt4(xp[s2]);
        float4 f3 = cvt4(xp[s3]);
        acc.x += (f0.x + f1.x) + (f2.x + f3.x);
        acc.y += (f0.y + f1.y) + (f2.y + f3.y);
        acc.z += (f0.z + f1.z) + (f2.z + f3.z);
        acc.w += (f0.w + f1.w) + (f2.w + f3.w);
    }
    for (; e < r1; e++) {
        float4 f0 = cvt4(xp[(uint32_t)g_col[e] * 32u + l]);
        acc.x += f0.x; acc.y += f0.y; acc.z += f0.z; acc.w += f0.w;
    }
    acc.x *= wd; acc.y *= wd; acc.z *= wd; acc.w *= wd;
    __half2 h0 = __floats2half2_rn(acc.x, acc.y);
    __half2 h1 = __floats2half2_rn(acc.z, acc.w);
    uint2 u;
    u.x = *reinterpret_cast<unsigned*>(&h0);
    u.y = *reinterpret_cast<unsigned*>(&h1);
    reinterpret_cast<uint2*>(g_aggh)[d * 32u + l] = u;
}

// ---------------- mma.sync GEMM + fused epilogue ----------------
// smem layout (bytes from dynamic base):
#define SM_BIAS   0                       // 128 f32
#define SM_PRELU  512                     // 128 f32
#define SM_BATCH  1024                    // 128 int
#define SM_A      2048                    // 128 x LDAH halves = 34816B (padded)
#define SM_B      (SM_A + 128 * LDAH * 2) // 34816B
#define SM_D      SM_A                    // reuse: 128 x LDD f32 = 66560B
#define SM_TOTAL  (SM_B + 128 * LDAH * 2) // 71680

#define LDSM_X4(r0, r1, r2, r3, addr) \
    asm volatile("ldmatrix.sync.aligned.m8n8.x4.shared.b16 {%0,%1,%2,%3}, [%4];" \
                 : "=r"(r0), "=r"(r1), "=r"(r2), "=r"(r3) : "r"(addr))

#define MMA16816(c, a0, a1, a2, a3, b0, b1) \
    asm volatile("mma.sync.aligned.m16n8k16.row.col.f32.f16.f16.f32 " \
                 "{%0,%1,%2,%3}, {%4,%5,%6,%7}, {%8,%9}, {%0,%1,%2,%3};" \
                 : "+f"((c)[0]), "+f"((c)[1]), "+f"((c)[2]), "+f"((c)[3]) \
                 : "r"(a0), "r"(a1), "r"(a2), "r"(a3), "r"(b0), "r"(b1))

__global__ __launch_bounds__(256) void k_mma_epi(const float* __restrict__ bias,
                                                 const float* __restrict__ pa,
                                                 const int* __restrict__ batch) {
    extern __shared__ __align__(1024) char sm[];
    int t = threadIdx.x;
    int w = t >> 5, l = t & 31;
    int row0 = blockIdx.x * TILE_M;

    // stage A tile (rows row0..row0+127) and B = W^T into padded smem
    for (int i = t; i < 2048; i += 256) {
        int r = i >> 4, c8 = i & 15;   // r: row, c8: 16B chunk (8 halves)
        uint4 va = reinterpret_cast<const uint4*>(g_aggh)[(size_t)(row0 + r) * 16 + c8];
        *reinterpret_cast<uint4*>(sm + SM_A + (r * LDAH + c8 * 8) * 2) = va;
        uint4 vb = reinterpret_cast<const uint4*>(g_wt)[i];
        *reinterpret_cast<uint4*>(sm + SM_B + (r * LDAH + c8 * 8) * 2) = vb;
    }
    for (int i = t; i < D_H; i += 256) {
        reinterpret_cast<float*>(sm + SM_BIAS)[i] = bias[i];
        reinterpret_cast<float*>(sm + SM_PRELU)[i] = pa[i];
        int rg = row0 + i;
        reinterpret_cast<int*>(sm + SM_BATCH)[i] = batch[rg < N_NODES ? rg : N_NODES - 1];
    }
    __syncthreads();

    uint32_t sA = smem_u32(sm + SM_A);
    uint32_t sB = smem_u32(sm + SM_B);

    // preload all 8 A k-chunk fragments for this warp's 16-row band
    uint32_t a[8][4];
    {
        uint32_t base = sA + ((w * 16 + (l & 15)) * LDAH + (l >> 4) * 8) * 2;
        #pragma unroll
        for (int k = 0; k < 8; k++)
            LDSM_X4(a[k][0], a[k][1], a[k][2], a[k][3], base + k * 32);
    }

    float acc[16][4];
    #pragma unroll
    for (int nb = 0; nb < 16; nb++)
        #pragma unroll
        for (int j = 0; j < 4; j++) acc[nb][j] = 0.f;

    uint32_t bbase = sB + ((((l >> 4) * 8) + (l & 7)) * LDAH + ((l >> 3) & 1) * 8) * 2;
    #pragma unroll
    for (int k = 0; k < 8; k++) {
        #pragma unroll
        for (int nbp = 0; nbp < 8; nbp++) {
            uint32_t b0, b1, b2, b3;
            LDSM_X4(b0, b1, b2, b3, bbase + (nbp * 16 * LDAH) * 2 + k * 32);
            MMA16816(acc[2 * nbp], a[k][0], a[k][1], a[k][2], a[k][3], b0, b1);
            MMA16816(acc[2 * nbp + 1], a[k][0], a[k][1], a[k][2], a[k][3], b2, b3);
        }
    }

    __syncthreads();   // done reading A/B; D region reuses A/B smem

    // epilogue: +bias, PReLU, row sumsq (quad shfl), normalize, stage to smem D
    {
        const float* sBias = reinterpret_cast<const float*>(sm + SM_BIAS);
        const float* sPrelu = reinterpret_cast<const float*>(sm + SM_PRELU);
        float* sD = reinterpret_cast<float*>(sm + SM_D);
        int quad = l >> 2, qlane = l & 3;
        int r_lo = w * 16 + quad, r_hi = r_lo + 8;

        float ss_lo = 0.f, ss_hi = 0.f;
        #pragma unroll
        for (int nb = 0; nb < 16; nb++) {
            int c0 = nb * 8 + qlane * 2;
            float b0 = sBias[c0], b1 = sBias[c0 + 1];
            float p0 = sPrelu[c0], p1 = sPrelu[c0 + 1];
            float v0 = acc[nb][0] + b0; v0 = v0 > 0.f ? v0 : v0 * p0;
            float v1 = acc[nb][1] + b1; v1 = v1 > 0.f ? v1 : v1 * p1;
            float v2 = acc[nb][2] + b0; v2 = v2 > 0.f ? v2 : v2 * p0;
            float v3 = acc[nb][3] + b1; v3 = v3 > 0.f ? v3 : v3 * p1;
            acc[nb][0] = v0; acc[nb][1] = v1; acc[nb][2] = v2; acc[nb][3] = v3;
            ss_lo += v0 * v0 + v1 * v1;
            ss_hi += v2 * v2 + v3 * v3;
        }
        ss_lo += __shfl_xor_sync(0xffffffffu, ss_lo, 1);
        ss_lo += __shfl_xor_sync(0xffffffffu, ss_lo, 2);
        ss_hi += __shfl_xor_sync(0xffffffffu, ss_hi, 1);
        ss_hi += __shfl_xor_sync(0xffffffffu, ss_hi, 2);
        float inv_lo = rsqrtf(fmaxf(ss_lo, 1e-24f));
        float inv_hi = rsqrtf(fmaxf(ss_hi, 1e-24f));

        #pragma unroll
        for (int nb = 0; nb < 16; nb++) {
            int c0 = nb * 8 + qlane * 2;
            *reinterpret_cast<float2*>(sD + r_lo * LDD + c0) =
                make_float2(acc[nb][0] * inv_lo, acc[nb][1] * inv_lo);
            *reinterpret_cast<float2*>(sD + r_hi * LDD + c0) =
                make_float2(acc[nb][2] * inv_hi, acc[nb][3] * inv_hi);
        }
    }
    __syncthreads();

    // pooling: 2 threads per column (rows 0-63 / 64-127), run-based flush to global
    {
        int c = t & 127;
        int r0 = (t >> 7) * 64;
        int nvalid = N_NODES - row0; if (nvalid > TILE_M) nvalid = TILE_M;
        int rend = r0 + 64; if (rend > nvalid) rend = nvalid;
        const float* sD = reinterpret_cast<const float*>(sm + SM_D);
        const int* sBatch = reinterpret_cast<const int*>(sm + SM_BATCH);
        int cur = -1;
        float acc2 = 0.f;
        for (int r = r0; r < rend; r++) {
            int g = sBatch[r];
            if (g != cur) {
                if (cur >= 0) atomicAdd(&g_pooled[cur * D_H + c], acc2);
                cur = g; acc2 = 0.f;
            }
            acc2 += sD[r * LDD + c];
        }
        if (cur >= 0) atomicAdd(&g_pooled[cur * D_H + c], acc2);
    }
}

// final output + reset state (deg, pooled, lookback) for the next call
__global__ void k_final(float* __restrict__ out) {
    int i = blockIdx.x * blockDim.x + threadIdx.x;
    if (i < N_GRAPHS * D_H) {
        int g = i >> 7;
        float c = (float)(g_bound[g + 1] - g_bound[g]);
        out[i] = g_pooled[i] / fmaxf(c, 1.f);
        g_pooled[i] = 0.f;
    }
    if (i < N_NODES) g_deg[i] = 0;
    if (i < NBLK) g_blk_pack[i] = 0ULL;
}

// ---------------- launcher ----------------
extern "C" void kernel_launch(void* const* d_in, const int* in_sizes, int n_in,
                              void* d_out, int out_size) {
    const float* x     = (const float*)d_in[0];
    const int*   ei    = (const int*)d_in[1];
    const int*   batch = (const int*)d_in[2];
    const float* W     = (const float*)d_in[3];
    const float* b     = (const float*)d_in[4];
    const float* pa    = (const float*)d_in[5];
    float* out = (float*)d_out;

    cudaFuncSetAttribute(k_mma_epi, cudaFuncAttributeMaxDynamicSharedMemorySize, SM_TOTAL);

    k_pre<<<(N_EDGES + 255) / 256, 256>>>(ei, batch, W);
    k_scanx<<<NBLK, SCAN_BLK>>>(x);
    k_fill<<<(N_EDGES + 255) / 256, 256>>>(ei);
    k_agg<<<(N_NODES * 32 + 255) / 256, 256>>>();
    k_mma_epi<<<N_TILES, 256, SM_TOTAL>>>(b, pa, batch);
    k_final<<<(N_NODES + 255) / 256, 256>>>(out);
}